// round 13
// baseline (speedup 1.0000x reference)
#include <cuda_runtime.h>

// Problem constants
#define I_ 3
#define H_ 2048
#define O_ 2
#define R_ 2
#define S_ 4
#define G_ 7
#define B_ 32
#define T_ 512
#define ALPHA_ 0.2f
#define DECAY_ 0.8f
#define NSTD_ 0.05f

#define NTHREADS 512
#define NWARPS (NTHREADS / 32)   // 16
#define EPT 4                    // 512*4 = 2048 = H
#define NPART (NWARPS * 4)       // 64 partials per buffer

// HW MUFU tanh (sm_75+), single SASS instruction
__device__ __forceinline__ float tanh_hw(float x) {
    float r;
    asm("tanh.approx.f32 %0, %1;" : "=f"(r) : "f"(x));
    return r;
}

__global__ __launch_bounds__(NTHREADS, 1)
void lowrank_rnn_kernel(const float* __restrict__ input,   // (B,T,I)
                        const float* __restrict__ noise,   // (B,T,H)
                        const float* __restrict__ wi,      // (I,S,G)
                        const float* __restrict__ unitwi,  // (I,S,1)
                        const float* __restrict__ m,       // (R,S,G)
                        const float* __restrict__ n,       // (R,S,G)
                        const float* __restrict__ unitm,   // (R,S,1)
                        const float* __restrict__ unitn,   // (R,S,1)
                        const float* __restrict__ wo,      // (O,S,G)
                        const float* __restrict__ h0,      // (S,G)
                        const float* __restrict__ unith0,  // (S,1)
                        const float* __restrict__ bias,    // (S,1)
                        const float* __restrict__ gb,      // (G,H)
                        const float* __restrict__ uv,      // (1,H)
                        const float* __restrict__ sup,     // (S,H)
                        float* __restrict__ out)           // out(B,T,O) ++ traj(B,T,H)
{
    const int b    = blockIdx.x;
    const int tid  = threadIdx.x;
    const int lane = tid & 31;
    const int warp = tid >> 5;
    const unsigned FULL = 0xffffffffu;

    __shared__ float s_red[2 * NPART];

    // ------------------------------------------------------------------
    // Phase 1: per-element effective weights in registers (one-time).
    // ALPHA folded into c_m* / c_wi*.
    // ------------------------------------------------------------------
    float hreg[EPT];
    float c_m0[EPT], c_m1[EPT], c_n0[EPT], c_n1[EPT];
    float c_wo0[EPT], c_wo1[EPT], c_bias[EPT];
    float c_wi0[EPT], c_wi1[EPT], c_wi2[EPT];

#pragma unroll
    for (int e = 0; e < EPT; e++) {
        const int hidx = tid * EPT + e;
        float gvec[G_];
#pragma unroll
        for (int g = 0; g < G_; g++) gvec[g] = gb[g * H_ + hidx];
        const float uvh = uv[hidx];

        float awi0 = 0.f, awi1 = 0.f, awi2 = 0.f;
        float am0 = 0.f, am1 = 0.f, an0 = 0.f, an1 = 0.f;
        float awo0 = 0.f, awo1 = 0.f, ah0 = 0.f, ab = 0.f;

#pragma unroll
        for (int s = 0; s < S_; s++) {
            const float su = sup[s * H_ + hidx];

            float d0 = 0.f, d1 = 0.f, d2 = 0.f;
#pragma unroll
            for (int g = 0; g < G_; g++) {
                d0 += wi[(0 * S_ + s) * G_ + g] * gvec[g];
                d1 += wi[(1 * S_ + s) * G_ + g] * gvec[g];
                d2 += wi[(2 * S_ + s) * G_ + g] * gvec[g];
            }
            awi0 += (d0 + unitwi[0 * S_ + s] * uvh) * su;
            awi1 += (d1 + unitwi[1 * S_ + s] * uvh) * su;
            awi2 += (d2 + unitwi[2 * S_ + s] * uvh) * su;

            float dm0 = 0.f, dm1 = 0.f, dn0 = 0.f, dn1 = 0.f;
#pragma unroll
            for (int g = 0; g < G_; g++) {
                dm0 += m[(0 * S_ + s) * G_ + g] * gvec[g];
                dm1 += m[(1 * S_ + s) * G_ + g] * gvec[g];
                dn0 += n[(0 * S_ + s) * G_ + g] * gvec[g];
                dn1 += n[(1 * S_ + s) * G_ + g] * gvec[g];
            }
            am0 += (dm0 + unitm[0 * S_ + s] * uvh) * su;
            am1 += (dm1 + unitm[1 * S_ + s] * uvh) * su;
            an0 += (dn0 + unitn[0 * S_ + s] * uvh) * su;
            an1 += (dn1 + unitn[1 * S_ + s] * uvh) * su;

            float do0 = 0.f, do1 = 0.f, dh = 0.f;
#pragma unroll
            for (int g = 0; g < G_; g++) {
                do0 += wo[(0 * S_ + s) * G_ + g] * gvec[g];
                do1 += wo[(1 * S_ + s) * G_ + g] * gvec[g];
                dh  += h0[s * G_ + g] * gvec[g];
            }
            awo0 += do0 * su;
            awo1 += do1 * su;
            ah0  += dh * su + unith0[s] * uvh * su;
            ab   += bias[s] * uvh * su;
        }
        hreg[e]  = ah0;
        c_m0[e]  = ALPHA_ * am0;  c_m1[e]  = ALPHA_ * am1;
        c_n0[e]  = an0;           c_n1[e]  = an1;
        c_wo0[e] = awo0;          c_wo1[e] = awo1;
        c_bias[e] = ab;
        c_wi0[e] = ALPHA_ * awi0; c_wi1[e] = ALPHA_ * awi1;
        c_wi2[e] = ALPHA_ * awi2;
    }

    // ------------------------------------------------------------------
    // Phase 2: recurrence.
    //   Pre-barrier: ONLY the warp tree + STS (earliest possible arrival;
    //   BAR.SYNC defers blocking to the first s_red consumer).
    //   Post-barrier, before the s_red LDS: traj STG, prefetch LDGs, and
    //   base FMAs — independent work that issues while the barrier drains.
    // ------------------------------------------------------------------
    const float* zb = noise + (size_t)b * T_ * H_;
    const float* xb = input + (size_t)b * T_ * I_;
    float* outp  = out + (size_t)b * T_ * O_;
    float* trajp = out + (size_t)B_ * T_ * O_ + (size_t)b * T_ * H_;

    // pr for r_0 = tanh(h_0)
    float4 pr = make_float4(0.f, 0.f, 0.f, 0.f);
#pragma unroll
    for (int e = 0; e < EPT; e++) {
        float r = tanh_hw(hreg[e]);
        pr.x = fmaf(r, c_n0[e], pr.x);
        pr.y = fmaf(r, c_n1[e], pr.y);
        pr.z = fmaf(r, c_wo0[e], pr.z);
        pr.w = fmaf(r, c_wo1[e], pr.w);
    }

    // Prefetch noise / input two steps ahead
    float4 z0 = *(const float4*)(zb + 0 * (size_t)H_ + tid * 4);
    float4 z1 = *(const float4*)(zb + 1 * (size_t)H_ + tid * 4);
    float xA0 = xb[0], xA1 = xb[1], xA2 = xb[2];
    float xB0 = xb[3], xB1 = xb[4], xB2 = xb[5];

    for (int t = 0; t < T_; t++) {
        const int buf = t & 1;

        // ---- stage A: warp-level folded reduce (6 SHFL) + STS ----
        {
            const bool k1 = !(lane & 1);
            float sA = k1 ? pr.z : pr.x;
            float rA = __shfl_xor_sync(FULL, sA, 1);
            float v0 = (k1 ? pr.x : pr.z) + rA;
            float sB = k1 ? pr.w : pr.y;
            float rB = __shfl_xor_sync(FULL, sB, 1);
            float v1 = (k1 ? pr.y : pr.w) + rB;
            const bool k2 = !(lane & 2);
            float sC = k2 ? v1 : v0;
            float rC = __shfl_xor_sync(FULL, sC, 2);
            float v  = (k2 ? v0 : v1) + rC;
            v += __shfl_xor_sync(FULL, v, 4);
            v += __shfl_xor_sync(FULL, v, 8);
            v += __shfl_xor_sync(FULL, v, 16);
            if (lane < 4) s_red[buf * NPART + warp * 4 + lane] = v;
        }

        __syncthreads();   // arrive EARLY; blocking deferred to s_red LDS

        // ---- post-barrier independent work (issues during bar drain) ----
        if (t > 0) {
            *(float4*)(trajp + (size_t)(t - 1) * H_ + tid * 4) =
                make_float4(hreg[0], hreg[1], hreg[2], hreg[3]);
        }
        const int tp = (t + 2 < T_) ? (t + 2) : (T_ - 1);
        float4 z2 = *(const float4*)(zb + (size_t)tp * H_ + tid * 4);
        const float xC0 = xb[tp * I_ + 0];
        const float xC1 = xb[tp * I_ + 1];
        const float xC2 = xb[tp * I_ + 2];

        float base[EPT];
        {
            const float zarr[EPT] = {z0.x, z0.y, z0.z, z0.w};
#pragma unroll
            for (int e = 0; e < EPT; e++) {
                float bb = fmaf(hreg[e], DECAY_, c_bias[e]);
                bb = fmaf(zarr[e], NSTD_, bb);
                bb = fmaf(xA0, c_wi0[e], bb);
                bb = fmaf(xA1, c_wi1[e], bb);
                bb = fmaf(xA2, c_wi2[e], bb);
                base[e] = bb;
            }
        }

        // ---- stage C: cross-warp reduce (first s_red consumer -> block) ----
        float Sn0, Sn1;
        {
            float u = s_red[buf * NPART + lane] + s_red[buf * NPART + 32 + lane];
            u += __shfl_xor_sync(FULL, u, 4);
            u += __shfl_xor_sync(FULL, u, 8);
            u += __shfl_xor_sync(FULL, u, 16);
            // lane&3: 0 -> n0, 1 -> wo0, 2 -> n1, 3 -> wo1
            Sn0 = __shfl_sync(FULL, u, 0);
            Sn1 = __shfl_sync(FULL, u, 2);
            if (warp == 0 && t > 0) {
                if (lane == 1) outp[(t - 1) * O_ + 0] = u;
                if (lane == 3) outp[(t - 1) * O_ + 1] = u;
            }
        }

        // ---- stage D: h_{t+1}, HW tanh, next pr ----
        pr = make_float4(0.f, 0.f, 0.f, 0.f);
#pragma unroll
        for (int e = 0; e < EPT; e++) {
            float h = fmaf(Sn0, c_m0[e], fmaf(Sn1, c_m1[e], base[e]));
            hreg[e] = h;
            float r = tanh_hw(h);
            pr.x = fmaf(r, c_n0[e], pr.x);
            pr.y = fmaf(r, c_n1[e], pr.y);
            pr.z = fmaf(r, c_wo0[e], pr.z);
            pr.w = fmaf(r, c_wo1[e], pr.w);
        }

        z0 = z1; z1 = z2;
        xA0 = xB0; xA1 = xB1; xA2 = xB2;
        xB0 = xC0; xB1 = xC1; xB2 = xC2;
    }

    // ---- epilogue: traj[T-1] and out[T-1] = wo · tanh(h_T) ----
    {
        *(float4*)(trajp + (size_t)(T_ - 1) * H_ + tid * 4) =
            make_float4(hreg[0], hreg[1], hreg[2], hreg[3]);

        const int buf = T_ & 1;
        const bool k1 = !(lane & 1);
        float sA = k1 ? pr.z : pr.x;
        float rA = __shfl_xor_sync(FULL, sA, 1);
        float v0 = (k1 ? pr.x : pr.z) + rA;
        float sB = k1 ? pr.w : pr.y;
        float rB = __shfl_xor_sync(FULL, sB, 1);
        float v1 = (k1 ? pr.y : pr.w) + rB;
        const bool k2 = !(lane & 2);
        float sC = k2 ? v1 : v0;
        float rC = __shfl_xor_sync(FULL, sC, 2);
        float v  = (k2 ? v0 : v1) + rC;
        v += __shfl_xor_sync(FULL, v, 4);
        v += __shfl_xor_sync(FULL, v, 8);
        v += __shfl_xor_sync(FULL, v, 16);
        if (lane < 4) s_red[buf * NPART + warp * 4 + lane] = v;
        __syncthreads();
        if (warp == 0) {
            float u = s_red[buf * NPART + lane] + s_red[buf * NPART + 32 + lane];
            u += __shfl_xor_sync(FULL, u, 4);
            u += __shfl_xor_sync(FULL, u, 8);
            u += __shfl_xor_sync(FULL, u, 16);
            if (lane == 1) outp[(T_ - 1) * O_ + 0] = u;
            if (lane == 3) outp[(T_ - 1) * O_ + 1] = u;
        }
    }
}

extern "C" void kernel_launch(void* const* d_in, const int* in_sizes, int n_in,
                              void* d_out, int out_size) {
    (void)in_sizes; (void)n_in; (void)out_size;
    const float* input    = (const float*)d_in[0];
    const float* noise    = (const float*)d_in[1];
    const float* wi       = (const float*)d_in[2];
    const float* unitwi   = (const float*)d_in[3];
    const float* m        = (const float*)d_in[4];
    const float* n        = (const float*)d_in[5];
    const float* unitm    = (const float*)d_in[6];
    const float* unitn    = (const float*)d_in[7];
    const float* wo       = (const float*)d_in[8];
    const float* h0       = (const float*)d_in[9];
    const float* unith0   = (const float*)d_in[10];
    const float* bias     = (const float*)d_in[11];
    const float* gb       = (const float*)d_in[12];
    const float* uv       = (const float*)d_in[13];
    const float* sup      = (const float*)d_in[14];
    float* out            = (float*)d_out;

    lowrank_rnn_kernel<<<B_, NTHREADS>>>(input, noise, wi, unitwi, m, n, unitm,
                                         unitn, wo, h0, unith0, bias, gb, uv,
                                         sup, out);
}

// round 15
// speedup vs baseline: 1.0306x; 1.0306x over previous
#include <cuda_runtime.h>

// Problem constants
#define I_ 3
#define H_ 2048
#define O_ 2
#define R_ 2
#define S_ 4
#define G_ 7
#define B_ 32
#define T_ 512
#define ALPHA_ 0.2f
#define DECAY_ 0.8f
#define NSTD_ 0.05f

#define NTHREADS 512
#define NWARPS (NTHREADS / 32)   // 16
#define EPT 4                    // 512*4 = 2048 = H
#define NPART (NWARPS * 4)       // 64 partials per buffer

// HW MUFU tanh (sm_75+), single SASS instruction
__device__ __forceinline__ float tanh_hw(float x) {
    float r;
    asm("tanh.approx.f32 %0, %1;" : "=f"(r) : "f"(x));
    return r;
}

__global__ __launch_bounds__(NTHREADS, 1)
void lowrank_rnn_kernel(const float* __restrict__ input,   // (B,T,I)
                        const float* __restrict__ noise,   // (B,T,H)
                        const float* __restrict__ wi,      // (I,S,G)
                        const float* __restrict__ unitwi,  // (I,S,1)
                        const float* __restrict__ m,       // (R,S,G)
                        const float* __restrict__ n,       // (R,S,G)
                        const float* __restrict__ unitm,   // (R,S,1)
                        const float* __restrict__ unitn,   // (R,S,1)
                        const float* __restrict__ wo,      // (O,S,G)
                        const float* __restrict__ h0,      // (S,G)
                        const float* __restrict__ unith0,  // (S,1)
                        const float* __restrict__ bias,    // (S,1)
                        const float* __restrict__ gb,      // (G,H)
                        const float* __restrict__ uv,      // (1,H)
                        const float* __restrict__ sup,     // (S,H)
                        float* __restrict__ out)           // out(B,T,O) ++ traj(B,T,H)
{
    const int b    = blockIdx.x;
    const int tid  = threadIdx.x;
    const int lane = tid & 31;
    const int warp = tid >> 5;
    const unsigned FULL = 0xffffffffu;

    // double-buffered warp totals: float4 per warp, channels (n0,n1,wo0,wo1)
    __shared__ __align__(16) float4 s_red4[2][NWARPS];

    // ------------------------------------------------------------------
    // Phase 1: per-element effective weights in registers (one-time).
    // ALPHA folded into c_m* / c_wi*.
    // ------------------------------------------------------------------
    float hreg[EPT];
    float c_m0[EPT], c_m1[EPT], c_n0[EPT], c_n1[EPT];
    float c_wo0[EPT], c_wo1[EPT], c_bias[EPT];
    float c_wi0[EPT], c_wi1[EPT], c_wi2[EPT];

#pragma unroll
    for (int e = 0; e < EPT; e++) {
        const int hidx = tid * EPT + e;
        float gvec[G_];
#pragma unroll
        for (int g = 0; g < G_; g++) gvec[g] = gb[g * H_ + hidx];
        const float uvh = uv[hidx];

        float awi0 = 0.f, awi1 = 0.f, awi2 = 0.f;
        float am0 = 0.f, am1 = 0.f, an0 = 0.f, an1 = 0.f;
        float awo0 = 0.f, awo1 = 0.f, ah0 = 0.f, ab = 0.f;

#pragma unroll
        for (int s = 0; s < S_; s++) {
            const float su = sup[s * H_ + hidx];

            float d0 = 0.f, d1 = 0.f, d2 = 0.f;
#pragma unroll
            for (int g = 0; g < G_; g++) {
                d0 += wi[(0 * S_ + s) * G_ + g] * gvec[g];
                d1 += wi[(1 * S_ + s) * G_ + g] * gvec[g];
                d2 += wi[(2 * S_ + s) * G_ + g] * gvec[g];
            }
            awi0 += (d0 + unitwi[0 * S_ + s] * uvh) * su;
            awi1 += (d1 + unitwi[1 * S_ + s] * uvh) * su;
            awi2 += (d2 + unitwi[2 * S_ + s] * uvh) * su;

            float dm0 = 0.f, dm1 = 0.f, dn0 = 0.f, dn1 = 0.f;
#pragma unroll
            for (int g = 0; g < G_; g++) {
                dm0 += m[(0 * S_ + s) * G_ + g] * gvec[g];
                dm1 += m[(1 * S_ + s) * G_ + g] * gvec[g];
                dn0 += n[(0 * S_ + s) * G_ + g] * gvec[g];
                dn1 += n[(1 * S_ + s) * G_ + g] * gvec[g];
            }
            am0 += (dm0 + unitm[0 * S_ + s] * uvh) * su;
            am1 += (dm1 + unitm[1 * S_ + s] * uvh) * su;
            an0 += (dn0 + unitn[0 * S_ + s] * uvh) * su;
            an1 += (dn1 + unitn[1 * S_ + s] * uvh) * su;

            float do0 = 0.f, do1 = 0.f, dh = 0.f;
#pragma unroll
            for (int g = 0; g < G_; g++) {
                do0 += wo[(0 * S_ + s) * G_ + g] * gvec[g];
                do1 += wo[(1 * S_ + s) * G_ + g] * gvec[g];
                dh  += h0[s * G_ + g] * gvec[g];
            }
            awo0 += do0 * su;
            awo1 += do1 * su;
            ah0  += dh * su + unith0[s] * uvh * su;
            ab   += bias[s] * uvh * su;
        }
        hreg[e]  = ah0;
        c_m0[e]  = ALPHA_ * am0;  c_m1[e]  = ALPHA_ * am1;
        c_n0[e]  = an0;           c_n1[e]  = an1;
        c_wo0[e] = awo0;          c_wo1[e] = awo1;
        c_bias[e] = ab;
        c_wi0[e] = ALPHA_ * awi0; c_wi1[e] = ALPHA_ * awi1;
        c_wi2[e] = ALPHA_ * awi2;
    }

    // ------------------------------------------------------------------
    // Phase 2: recurrence (R12 schedule; stage A = parallel 4-ch butterfly,
    // ONE STS.128 per warp — 16 STS in flight at the barrier, not 64).
    // ------------------------------------------------------------------
    const float* zb = noise + (size_t)b * T_ * H_;
    const float* xb = input + (size_t)b * T_ * I_;
    float* outp  = out + (size_t)b * T_ * O_;
    float* trajp = out + (size_t)B_ * T_ * O_ + (size_t)b * T_ * H_;

    // pr for r_0 = tanh(h_0): (x=n0, y=n1, z=wo0, w=wo1)
    float4 pr = make_float4(0.f, 0.f, 0.f, 0.f);
#pragma unroll
    for (int e = 0; e < EPT; e++) {
        float r = tanh_hw(hreg[e]);
        pr.x = fmaf(r, c_n0[e], pr.x);
        pr.y = fmaf(r, c_n1[e], pr.y);
        pr.z = fmaf(r, c_wo0[e], pr.z);
        pr.w = fmaf(r, c_wo1[e], pr.w);
    }

    // Prefetch noise / input two steps ahead
    float4 z0 = *(const float4*)(zb + 0 * (size_t)H_ + tid * 4);
    float4 z1 = *(const float4*)(zb + 1 * (size_t)H_ + tid * 4);
    float xA0 = xb[0], xA1 = xb[1], xA2 = xb[2];
    float xB0 = xb[3], xB1 = xb[4], xB2 = xb[5];

    for (int t = 0; t < T_; t++) {
        const int buf = t & 1;

        // ---- stage A: plain 4-channel butterfly (5 levels, parallel) ----
        {
#pragma unroll
            for (int off = 16; off; off >>= 1) {
                pr.x += __shfl_xor_sync(FULL, pr.x, off);
                pr.y += __shfl_xor_sync(FULL, pr.y, off);
                pr.z += __shfl_xor_sync(FULL, pr.z, off);
                pr.w += __shfl_xor_sync(FULL, pr.w, off);
            }
            if (lane == 0) s_red4[buf][warp] = pr;   // ONE STS.128 per warp
        }

        // ---- stage B (shadow work, independent of the reduction) ----
        float base[EPT];
        {
            const float zarr[EPT] = {z0.x, z0.y, z0.z, z0.w};
#pragma unroll
            for (int e = 0; e < EPT; e++) {
                float bb = fmaf(hreg[e], DECAY_, c_bias[e]);
                bb = fmaf(zarr[e], NSTD_, bb);
                bb = fmaf(xA0, c_wi0[e], bb);
                bb = fmaf(xA1, c_wi1[e], bb);
                bb = fmaf(xA2, c_wi2[e], bb);
                base[e] = bb;
            }
        }
        if (t > 0) {
            *(float4*)(trajp + (size_t)(t - 1) * H_ + tid * 4) =
                make_float4(hreg[0], hreg[1], hreg[2], hreg[3]);
        }
        const int tp = (t + 2 < T_) ? (t + 2) : (T_ - 1);
        float4 z2 = *(const float4*)(zb + (size_t)tp * H_ + tid * 4);
        const float xC0 = xb[tp * I_ + 0];
        const float xC1 = xb[tp * I_ + 1];
        const float xC2 = xb[tp * I_ + 2];

        __syncthreads();

        // ---- stage C: cross-warp reduce over 64 floats (16 float4) ----
        float Sn0, Sn1;
        {
            const float* s = (const float*)&s_red4[buf][0];
            float u = s[lane] + s[32 + lane];
            u += __shfl_xor_sync(FULL, u, 4);
            u += __shfl_xor_sync(FULL, u, 8);
            u += __shfl_xor_sync(FULL, u, 16);
            // lane&3: 0 -> n0, 1 -> n1, 2 -> wo0, 3 -> wo1 (natural order)
            Sn0 = __shfl_sync(FULL, u, 0);
            Sn1 = __shfl_sync(FULL, u, 1);
            if (warp == 0 && t > 0) {
                if (lane == 2) outp[(t - 1) * O_ + 0] = u;
                if (lane == 3) outp[(t - 1) * O_ + 1] = u;
            }
        }

        // ---- stage D: h_{t+1}, HW tanh, next pr ----
        pr = make_float4(0.f, 0.f, 0.f, 0.f);
#pragma unroll
        for (int e = 0; e < EPT; e++) {
            float h = fmaf(Sn0, c_m0[e], fmaf(Sn1, c_m1[e], base[e]));
            hreg[e] = h;
            float r = tanh_hw(h);
            pr.x = fmaf(r, c_n0[e], pr.x);
            pr.y = fmaf(r, c_n1[e], pr.y);
            pr.z = fmaf(r, c_wo0[e], pr.z);
            pr.w = fmaf(r, c_wo1[e], pr.w);
        }

        z0 = z1; z1 = z2;
        xA0 = xB0; xA1 = xB1; xA2 = xB2;
        xB0 = xC0; xB1 = xC1; xB2 = xC2;
    }

    // ---- epilogue: traj[T-1] and out[T-1] = wo · tanh(h_T) ----
    {
        *(float4*)(trajp + (size_t)(T_ - 1) * H_ + tid * 4) =
            make_float4(hreg[0], hreg[1], hreg[2], hreg[3]);

        const int buf = T_ & 1;
#pragma unroll
        for (int off = 16; off; off >>= 1) {
            pr.x += __shfl_xor_sync(FULL, pr.x, off);
            pr.y += __shfl_xor_sync(FULL, pr.y, off);
            pr.z += __shfl_xor_sync(FULL, pr.z, off);
            pr.w += __shfl_xor_sync(FULL, pr.w, off);
        }
        if (lane == 0) s_red4[buf][warp] = pr;
        __syncthreads();
        if (warp == 0) {
            const float* s = (const float*)&s_red4[buf][0];
            float u = s[lane] + s[32 + lane];
            u += __shfl_xor_sync(FULL, u, 4);
            u += __shfl_xor_sync(FULL, u, 8);
            u += __shfl_xor_sync(FULL, u, 16);
            if (lane == 2) outp[(T_ - 1) * O_ + 0] = u;
            if (lane == 3) outp[(T_ - 1) * O_ + 1] = u;
        }
    }
}

extern "C" void kernel_launch(void* const* d_in, const int* in_sizes, int n_in,
                              void* d_out, int out_size) {
    (void)in_sizes; (void)n_in; (void)out_size;
    const float* input    = (const float*)d_in[0];
    const float* noise    = (const float*)d_in[1];
    const float* wi       = (const float*)d_in[2];
    const float* unitwi   = (const float*)d_in[3];
    const float* m        = (const float*)d_in[4];
    const float* n        = (const float*)d_in[5];
    const float* unitm    = (const float*)d_in[6];
    const float* unitn    = (const float*)d_in[7];
    const float* wo       = (const float*)d_in[8];
    const float* h0       = (const float*)d_in[9];
    const float* unith0   = (const float*)d_in[10];
    const float* bias     = (const float*)d_in[11];
    const float* gb       = (const float*)d_in[12];
    const float* uv       = (const float*)d_in[13];
    const float* sup      = (const float*)d_in[14];
    float* out            = (float*)d_out;

    lowrank_rnn_kernel<<<B_, NTHREADS>>>(input, noise, wi, unitwi, m, n, unitm,
                                         unitn, wo, h0, unith0, bias, gb, uv,
                                         sup, out);
}